// round 7
// baseline (speedup 1.0000x reference)
#include <cuda_runtime.h>
#include <cuda_bf16.h>
#include <stdint.h>

#define B_     2
#define N_     65536
#define M_     16384
#define K_     32
#define KP_    15
#define DIN_   64
#define DOUT_  128
#define KTOT   960           // KP_*DIN_
#define SHADOW (-1000.0f)

// ---------------------------------------------------------------------------
// Scratch (__device__ globals per no-allocation rule)
// ---------------------------------------------------------------------------
__device__ float g_featT[(size_t)B_ * N_ * DIN_];                       // 33.5 MB
__device__ __align__(16) __nv_bfloat16 g_whi[(size_t)B_ * M_ * KTOT];   // 60 MB
__device__ __align__(16) __nv_bfloat16 g_wlo[(size_t)B_ * M_ * KTOT];   // 60 MB
__device__ __align__(16) __nv_bfloat16 g_bhi[DOUT_ * KTOT];             // W^T hi
__device__ __align__(16) __nv_bfloat16 g_blo[DOUT_ * KTOT];             // W^T lo

// ---------------------------------------------------------------------------
// helpers
// ---------------------------------------------------------------------------
__device__ __forceinline__ uint32_t smem_u32(const void* p) {
    uint32_t a;
    asm("{ .reg .u64 t; cvta.to.shared.u64 t, %1; cvt.u32.u64 %0, t; }"
        : "=r"(a) : "l"(p));
    return a;
}
__device__ __forceinline__ void ldsm4(uint32_t& r0, uint32_t& r1,
                                      uint32_t& r2, uint32_t& r3, uint32_t addr) {
    asm volatile("ldmatrix.sync.aligned.m8n8.x4.shared.b16 {%0,%1,%2,%3}, [%4];"
                 : "=r"(r0), "=r"(r1), "=r"(r2), "=r"(r3) : "r"(addr));
}
__device__ __forceinline__ void mma16816(float* c, const uint32_t* a,
                                         const uint32_t* b) {
    asm volatile("mma.sync.aligned.m16n8k16.row.col.f32.bf16.bf16.f32 "
                 "{%0,%1,%2,%3}, {%4,%5,%6,%7}, {%8,%9}, {%0,%1,%2,%3};"
                 : "+f"(c[0]), "+f"(c[1]), "+f"(c[2]), "+f"(c[3])
                 : "r"(a[0]), "r"(a[1]), "r"(a[2]), "r"(a[3]),
                   "r"(b[0]), "r"(b[1]));
}
__device__ __forceinline__ void cpasync16(uint32_t dst, const void* src) {
    asm volatile("cp.async.ca.shared.global [%0], [%1], 16;" :: "r"(dst), "l"(src));
}
__device__ __forceinline__ void cp_commit() {
    asm volatile("cp.async.commit_group;" ::: "memory");
}
__device__ __forceinline__ void cp_wait1() {
    asm volatile("cp.async.wait_group 1;" ::: "memory");
}
__device__ __forceinline__ void cp_wait0() {
    asm volatile("cp.async.wait_group 0;" ::: "memory");
}

// ---------------------------------------------------------------------------
// Kernel 1: transpose features [B][Din][N] -> g_featT [B][N][Din]
// ---------------------------------------------------------------------------
__global__ void transpose_feat_kernel(const float* __restrict__ f)
{
    __shared__ float tile[32][33];
    const int b  = blockIdx.z;
    const int n0 = blockIdx.x * 32;
    const int d0 = blockIdx.y * 32;
    const int x = threadIdx.x, y = threadIdx.y;

    #pragma unroll
    for (int i = y; i < 32; i += 8)
        tile[i][x] = f[((size_t)b * DIN_ + (d0 + i)) * N_ + n0 + x];
    __syncthreads();
    #pragma unroll
    for (int i = y; i < 32; i += 8)
        g_featT[((size_t)b * N_ + (n0 + i)) * DIN_ + d0 + x] = tile[x][i];
}

// ---------------------------------------------------------------------------
// Kernel 1b: weights [Kp][Din][Dout] -> g_bhi/g_blo [Dout rows][KTOT cols]
// ---------------------------------------------------------------------------
__global__ void prep_w_kernel(const float* __restrict__ w)
{
    const int e = blockIdx.x * 256 + threadIdx.x;
    if (e >= KP_ * DIN_ * DOUT_) return;
    const int kp = e / DOUT_, o = e % DOUT_;
    const float v = w[e];
    const __nv_bfloat16 hi = __float2bfloat16(v);
    const __nv_bfloat16 lo = __float2bfloat16(v - __bfloat162float(hi));
    g_bhi[o * KTOT + kp] = hi;
    g_blo[o * KTOT + kp] = lo;
}

// ---------------------------------------------------------------------------
// Kernel 2: 16 points per CTA, 512 threads.
//   Phase 1/2: thread = (pt, k=lane) — rel coords stay in registers,
//   warp-shuffle max for m_dist, no integer div/mod anywhere.
//   Phase 3/4: thread = (pt, d4 = lane>>1, ph = lane&1) with acc[8][4]
//   (p-range split in half -> ~60 regs -> 2x residency vs R6).
// NOTE: neighbor_indices is int32 (JAX canonicalizes int64 -> int32).
// ---------------------------------------------------------------------------
#define PTS 16
__global__ __launch_bounds__(512)
void kpconv_weighted_kernel(const float* __restrict__ points_xyz,
                            const float* __restrict__ center_xyz,
                            const int* __restrict__ nidx,
                            const float* __restrict__ kernel_points)
{
    const int bm0  = blockIdx.x * PTS;
    const int b    = bm0 >> 14;         // 16 | 16384 -> one batch per block
    const int t    = threadIdx.x;
    const int pt   = t >> 5;            // warp id == point id
    const int lane = t & 31;
    const int bm   = bm0 + pt;

    __shared__ int   s_idx[PTS][K_];
    __shared__ float s_w[PTS][481];     // [pt][k*15+p] (+1 guard col)
    __shared__ float s_kp[KP_ * 3];

    if (t < KP_ * 3) s_kp[t] = kernel_points[t];

    // ---- phase 1: one (pt, k) per thread; coords stay in registers
    const int ii0 = nidx[(size_t)bm * K_ + lane];
    s_idx[pt][lane] = ii0;
    float px = SHADOW, py = SHADOW, pz = SHADOW;
    if ((unsigned)ii0 < (unsigned)N_) {
        const float* pp = points_xyz + ((size_t)b * N_ + ii0) * 3;
        px = pp[0]; py = pp[1]; pz = pp[2];
    }
    const float rx = px - center_xyz[bm * 3 + 0];
    const float ry = py - center_xyz[bm * 3 + 1];
    const float rz = pz - center_xyz[bm * 3 + 2];
    float md = sqrtf(rx * rx + ry * ry + rz * rz);
    #pragma unroll
    for (int o = 16; o; o >>= 1)
        md = fmaxf(md, __shfl_xor_sync(0xffffffffu, md, o));
    const float inv = 1.0f / (md / 2.1f + 1e-5f);

    __syncthreads();                    // s_kp visible

    // ---- phase 2: w[pt][k=lane][p]
    #pragma unroll
    for (int p = 0; p < KP_; ++p) {
        const float dx = rx - s_kp[p * 3 + 0] * md;
        const float dy = ry - s_kp[p * 3 + 1] * md;
        const float dz = rz - s_kp[p * 3 + 2] * md;
        const float w  = 1.0f - sqrtf(dx * dx + dy * dy + dz * dz) * inv;
        s_w[pt][lane * 15 + p] = fmaxf(w, 0.0f);
    }
    __syncthreads();

    // ---- phase 3: accumulate weighted[p][d] (p split in half per thread)
    const int d4 = lane >> 1, ph = lane & 1;
    const int pbase = ph * 8;
    float acc[8][4];
    #pragma unroll
    for (int j = 0; j < 8; ++j)
        #pragma unroll
        for (int q = 0; q < 4; ++q) acc[j][q] = 0.0f;

    const float* wrow = s_w[pt];
    #pragma unroll 4
    for (int k = 0; k < K_; ++k) {
        const int ii = s_idx[pt][k];
        if ((unsigned)ii < (unsigned)N_) {
            const float4 f = *(const float4*)(g_featT
                               + ((size_t)b * N_ + ii) * DIN_ + d4 * 4);
            #pragma unroll
            for (int j = 0; j < 8; ++j) {
                // ph=1,j=7 reads wrow[k*15+15] (in-bounds, result unused)
                const float wv = wrow[k * 15 + pbase + j];
                acc[j][0] += wv * f.x; acc[j][1] += wv * f.y;
                acc[j][2] += wv * f.z; acc[j][3] += wv * f.w;
            }
        }
    }

    // ---- phase 4: bf16 hi/lo split, coalesced 8B stores
    const size_t rowOff = (size_t)bm * KTOT + d4 * 4;
    const int np = 8 - ph;              // ph=1 owns only p=8..14
    #pragma unroll
    for (int j = 0; j < 8; ++j) {
        if (j < np) {
            const int p = pbase + j;
            __nv_bfloat16 h[4], l[4];
            #pragma unroll
            for (int q = 0; q < 4; ++q) {
                h[q] = __float2bfloat16(acc[j][q]);
                l[q] = __float2bfloat16(acc[j][q] - __bfloat162float(h[q]));
            }
            *(uint2*)&g_whi[rowOff + p * DIN_] = *(const uint2*)h;
            *(uint2*)&g_wlo[rowOff + p * DIN_] = *(const uint2*)l;
        }
    }
}

// ---------------------------------------------------------------------------
// Kernel 3: mma.sync bf16 GEMM, 3-term hi/lo split, cp.async double buffer
//   C[128x128] per CTA = A[128x960] @ W[960x128]; BK=32, 30 chunks
//   __launch_bounds__(256, 2): <=128 regs -> 2 CTAs/SM -> single wave (256<=296)
// ---------------------------------------------------------------------------
#define BK    32
#define LDS_  40                 // row stride (elements): 80B, ldsm conflict-free
#define ARR_BYTES  (128 * LDS_ * 2)          // 10240 B per array
#define STAGE_BYTES (4 * ARR_BYTES)          // Ah, Al, Bh, Bl
#define GEMM_SMEM  (2 * STAGE_BYTES)         // 81920 B

__global__ __launch_bounds__(256, 2)
void kpconv_mma_gemm(float* __restrict__ out)
{
    extern __shared__ __align__(16) char sm[];
    const uint32_t smem_base = smem_u32(sm);

    const int tid  = threadIdx.x;
    const int wid  = tid >> 5, lane = tid & 31;
    const int wm   = wid & 3;        // warp m-offset: wm*32
    const int wn   = wid >> 2;       // warp n-offset: wn*64
    const size_t rowBase = (size_t)blockIdx.x * 128;

    auto issue_chunk = [&](int c, int stage) {
        const uint32_t sb = smem_base + stage * STAGE_BYTES;
        #pragma unroll
        for (int i = 0; i < 8; ++i) {
            const int idx = tid + i * 256;
            const int arr = idx >> 9;           // 0..3
            const int rem = idx & 511;
            const int row = rem >> 2, seg = rem & 3;
            const uint32_t dst = sb + arr * ARR_BYTES + (row * LDS_ + seg * 8) * 2;
            const __nv_bfloat16* src;
            if (arr == 0)      src = g_whi + (rowBase + row) * KTOT + c * BK + seg * 8;
            else if (arr == 1) src = g_wlo + (rowBase + row) * KTOT + c * BK + seg * 8;
            else if (arr == 2) src = g_bhi + (size_t)row * KTOT + c * BK + seg * 8;
            else               src = g_blo + (size_t)row * KTOT + c * BK + seg * 8;
            cpasync16(dst, src);
        }
        cp_commit();
    };

    float acc[2][8][4];
    #pragma unroll
    for (int i = 0; i < 2; i++)
        #pragma unroll
        for (int j = 0; j < 8; j++)
            #pragma unroll
            for (int q = 0; q < 4; q++) acc[i][j][q] = 0.0f;

    // per-lane ldmatrix row/col patterns
    const int ltile = lane >> 3, lr = lane & 7;
    const int aRow = (ltile & 1) * 8 + lr;
    const int aCol = (ltile >> 1) * 8;
    const int bRow = (ltile >> 1) * 8 + lr;
    const int bCol = (ltile & 1) * 8;

    issue_chunk(0, 0);

    for (int c = 0; c < KTOT / BK; ++c) {
        if (c + 1 < KTOT / BK) { issue_chunk(c + 1, (c + 1) & 1); cp_wait1(); }
        else                   { cp_wait0(); }
        __syncthreads();

        const uint32_t sb  = smem_base + (c & 1) * STAGE_BYTES;
        const uint32_t pAh = sb;
        const uint32_t pAl = sb + ARR_BYTES;
        const uint32_t pBh = sb + 2 * ARR_BYTES;
        const uint32_t pBl = sb + 3 * ARR_BYTES;

        #pragma unroll
        for (int kk = 0; kk < 2; ++kk) {
            const int kcol = kk * 16;
            uint32_t afh[2][4], afl[2][4];
            #pragma unroll
            for (int mt = 0; mt < 2; ++mt) {
                const int row = wm * 32 + mt * 16 + aRow;
                const int col = kcol + aCol;
                const uint32_t off = (uint32_t)(row * LDS_ + col) * 2;
                ldsm4(afh[mt][0], afh[mt][1], afh[mt][2], afh[mt][3], pAh + off);
                ldsm4(afl[mt][0], afl[mt][1], afl[mt][2], afl[mt][3], pAl + off);
            }
            #pragma unroll
            for (int g = 0; g < 4; ++g) {
                const int row = wn * 64 + g * 16 + bRow;
                const int col = kcol + bCol;
                const uint32_t off = (uint32_t)(row * LDS_ + col) * 2;
                uint32_t bh[4], bl[4];
                ldsm4(bh[0], bh[1], bh[2], bh[3], pBh + off);
                ldsm4(bl[0], bl[1], bl[2], bl[3], pBl + off);
                #pragma unroll
                for (int half = 0; half < 2; ++half) {
                    const int nt = 2 * g + half;
                    #pragma unroll
                    for (int mt = 0; mt < 2; ++mt) {
                        mma16816(acc[mt][nt], afh[mt], bh + 2 * half);
                        mma16816(acc[mt][nt], afl[mt], bh + 2 * half);
                        mma16816(acc[mt][nt], afh[mt], bl + 2 * half);
                    }
                }
            }
        }
        __syncthreads();
    }

    // epilogue: c0:(r,c) c1:(r,c+1) c2:(r+8,c) c3:(r+8,c+1)
    const int bb     = (int)(rowBase >> 14);
    const int mLocal = (int)(rowBase & 16383);
    #pragma unroll
    for (int mt = 0; mt < 2; ++mt)
        #pragma unroll
        for (int nt = 0; nt < 8; ++nt) {
            const int m0 = mLocal + wm * 32 + mt * 16 + (lane >> 2);
            const int n0 = wn * 64 + nt * 8 + 2 * (lane & 3);
            float* o0 = out + ((size_t)bb * DOUT_ + n0) * M_ + m0;
            o0[0]      = acc[mt][nt][0];
            o0[M_]     = acc[mt][nt][1];
            o0[8]      = acc[mt][nt][2];
            o0[M_ + 8] = acc[mt][nt][3];
        }
}

// ---------------------------------------------------------------------------
extern "C" void kernel_launch(void* const* d_in, const int* in_sizes, int n_in,
                              void* d_out, int out_size)
{
    // Dispatch inputs by (pairwise-distinct) element count:
    const float* points_xyz    = nullptr;
    const float* features      = nullptr;
    const float* center_xyz    = nullptr;
    const int*   neighbor_idx  = nullptr;
    const float* kernel_points = nullptr;
    const float* weights       = nullptr;

    for (int i = 0; i < n_in; i++) {
        switch (in_sizes[i]) {
            case 393216:  points_xyz    = (const float*)d_in[i]; break;
            case 8388608: features      = (const float*)d_in[i]; break;
            case 98304:   center_xyz    = (const float*)d_in[i]; break;
            case 1048576: neighbor_idx  = (const int*)d_in[i];   break;
            case 45:      kernel_points = (const float*)d_in[i]; break;
            case 122880:  weights       = (const float*)d_in[i]; break;
            default: break;
        }
    }
    float* out = (float*)d_out;

    cudaFuncSetAttribute(kpconv_mma_gemm,
                         cudaFuncAttributeMaxDynamicSharedMemorySize, GEMM_SMEM);
    cudaFuncSetAttribute(kpconv_mma_gemm,
                         cudaFuncAttributePreferredSharedMemoryCarveout, 100);

    dim3 g1(N_ / 32, DIN_ / 32, B_);
    transpose_feat_kernel<<<g1, dim3(32, 8)>>>(features);

    prep_w_kernel<<<(KP_ * DIN_ * DOUT_ + 255) / 256, 256>>>(weights);

    kpconv_weighted_kernel<<<(B_ * M_) / PTS, 512>>>(points_xyz, center_xyz,
                                                     neighbor_idx, kernel_points);

    kpconv_mma_gemm<<<(B_ * M_) / 128, 256, GEMM_SMEM>>>(out);
}